// round 2
// baseline (speedup 1.0000x reference)
#include <cuda_runtime.h>

// ============================================================================
// ElementwiseTensorProducts: fully fused single-kernel fp32 baseline.
//
//   proj0: P0[t][0:64]=z0@W0l^T+b0l, P0[t][64:128]=z0@W0r^T+b0r
//   proj1: P1[t][i*128+0:64]=z1_i@W1l^T, P1[t][i*128+64:128]=z1_i@W1r^T
//   z0_o = [p00 | p110]  -> out0 = z0_o @ W0o^T + b0o
//   z1_o = [q011|q101|q111] (per i) -> out1 = z1_o @ W1o^T (K=192, chunked 3x64)
//
// Block = 256 threads = 8 warps, tile = 64 tokens (warp w -> tokens 8w..8w+7,
// lane l -> output channels 4l..4l+3). Weights staged transposed in smem
// ([k][j], row stride 132 floats for conflict-free float4 reads). All
// intermediates live in smem; no scratch global memory needed.
// ============================================================================

#define THREADS 256
#define TTILE   64
#define WS      132          // padded row stride (floats) of transposed weights

// smem layout (floats)
#define OFF_A   0            // 8192  : z0 tile / z1_i tile / z0_o / q tile
#define OFF_P0  8192         // 8192  : proj0 result [64][128]
#define OFF_P1  16384        // 24576 : proj1 result [64][384]
#define OFF_W   40960        // 16896 : transposed weight buffer [<=128][132]
#define SMEM_FLOATS 57856    // 231424 bytes

// C[t0..t0+7][4*lane..4*lane+3] += A[t][k] * Wt[k][j]   (A reads are warp-
// uniform broadcasts; Wt reads are 128 consecutive floats per row -> no
// bank conflicts)
__device__ __forceinline__ void gemm_tile(const float* __restrict__ sA, int lda,
                                          const float* __restrict__ sW, int K,
                                          float (&acc)[8][4], int t0, int lane) {
#pragma unroll 2
    for (int k = 0; k < K; k += 4) {
        float4 a[8];
#pragma unroll
        for (int tt = 0; tt < 8; ++tt)
            a[tt] = *(const float4*)&sA[(t0 + tt) * lda + k];
#pragma unroll
        for (int kk = 0; kk < 4; ++kk) {
            float4 w = *(const float4*)&sW[(k + kk) * WS + lane * 4];
#pragma unroll
            for (int tt = 0; tt < 8; ++tt) {
                float av = (kk == 0) ? a[tt].x : (kk == 1) ? a[tt].y
                         : (kk == 2) ? a[tt].z : a[tt].w;
                acc[tt][0] = fmaf(av, w.x, acc[tt][0]);
                acc[tt][1] = fmaf(av, w.y, acc[tt][1]);
                acc[tt][2] = fmaf(av, w.z, acc[tt][2]);
                acc[tt][3] = fmaf(av, w.w, acc[tt][3]);
            }
        }
    }
}

// Load W[j][k] (row-major, K=128 cols) transposed into sW[k*WS + jofs + j]
template <int K>
__device__ __forceinline__ void load_wt(const float* __restrict__ g, float* sW,
                                        int J, int jofs, int tid) {
    for (int e = tid; e < J * K; e += THREADS) {
        int j = e / K, k = e - j * K;
        sW[k * WS + jofs + j] = g[e];
    }
}

__global__ __launch_bounds__(THREADS, 1)
void etp_kernel(const float* __restrict__ z0, const float* __restrict__ z1,
                const float* __restrict__ W0l, const float* __restrict__ b0l,
                const float* __restrict__ W0r, const float* __restrict__ b0r,
                const float* __restrict__ W1l, const float* __restrict__ W1r,
                const float* __restrict__ W0o, const float* __restrict__ b0o,
                const float* __restrict__ W1o,
                float* __restrict__ out0, float* __restrict__ out1) {
    extern __shared__ float sm[];
    float* sA  = sm + OFF_A;
    float* sP0 = sm + OFF_P0;
    float* sP1 = sm + OFF_P1;
    float* sW  = sm + OFF_W;

    const int tid  = threadIdx.x;
    const int lane = tid & 31;
    const int warp = tid >> 5;
    const int t0   = warp * 8;
    const long tokbase = (long)blockIdx.x * TTILE;

    // ---- stage z0 tile + proj0 weights ----
    {
        const float4* src = (const float4*)(z0 + tokbase * 128);
        float4* dst = (float4*)sA;
        for (int e = tid; e < TTILE * 128 / 4; e += THREADS) dst[e] = src[e];
    }
    load_wt<128>(W0l, sW, 64, 0, tid);
    load_wt<128>(W0r, sW, 64, 64, tid);
    __syncthreads();

    // ---- proj0 ----
    {
        float acc[8][4];
#pragma unroll
        for (int m = 0; m < 4; ++m) {
            int j = lane * 4 + m;
            float b = (j < 64) ? b0l[j] : b0r[j - 64];
#pragma unroll
            for (int tt = 0; tt < 8; ++tt) acc[tt][m] = b;
        }
        gemm_tile(sA, 128, sW, 128, acc, t0, lane);
#pragma unroll
        for (int tt = 0; tt < 8; ++tt)
            *(float4*)&sP0[(t0 + tt) * 128 + lane * 4] =
                make_float4(acc[tt][0], acc[tt][1], acc[tt][2], acc[tt][3]);
    }
    __syncthreads();

    // ---- proj1 (i = 0..2, weights stay resident) ----
    load_wt<128>(W1l, sW, 64, 0, tid);
    load_wt<128>(W1r, sW, 64, 64, tid);
    for (int i = 0; i < 3; ++i) {
        // stage z1[:, i, :] tile (token row stride 384 floats)
        for (int e = tid; e < 2048; e += THREADS) {
            int t = e >> 5, q = e & 31;
            ((float4*)sA)[e] =
                *(const float4*)(z1 + (tokbase + t) * 384 + i * 128 + q * 4);
        }
        __syncthreads();   // z1 tile + (first iter) W1lr ready; prior sA readers done
        float acc[8][4];
#pragma unroll
        for (int tt = 0; tt < 8; ++tt)
#pragma unroll
            for (int m = 0; m < 4; ++m) acc[tt][m] = 0.f;
        gemm_tile(sA, 128, sW, 128, acc, t0, lane);
#pragma unroll
        for (int tt = 0; tt < 8; ++tt)
            *(float4*)&sP1[(t0 + tt) * 384 + i * 128 + lane * 4] =
                make_float4(acc[tt][0], acc[tt][1], acc[tt][2], acc[tt][3]);
        __syncthreads();   // allow sA reuse next i / next phase
    }

    // ---- build z0_o = [p00 | p110] into sA; stage W0o ----
    for (int e = tid; e < 8192; e += THREADS) {
        int t = e >> 7, k = e & 127;
        float v;
        const float* p = &sP1[t * 384];
        if (k < 64) {
            v = sP0[t * 128 + k] * sP0[t * 128 + 64 + k];
        } else {
            int r = k - 64;
            v = p[r] * p[64 + r] + p[128 + r] * p[192 + r] + p[256 + r] * p[320 + r];
        }
        sA[e] = v;
    }
    load_wt<128>(W0o, sW, 128, 0, tid);
    __syncthreads();

    // ---- out0 ----
    {
        float acc[8][4];
#pragma unroll
        for (int m = 0; m < 4; ++m) {
            float b = b0o[lane * 4 + m];
#pragma unroll
            for (int tt = 0; tt < 8; ++tt) acc[tt][m] = b;
        }
        gemm_tile(sA, 128, sW, 128, acc, t0, lane);
#pragma unroll
        for (int tt = 0; tt < 8; ++tt)
            *(float4*)&out0[(tokbase + t0 + tt) * 128 + lane * 4] =
                make_float4(acc[tt][0], acc[tt][1], acc[tt][2], acc[tt][3]);
    }

    // ---- out1: K=192 GEMM, chunked into 3 slabs of 64 k each ----
    float acc1[3][8][4];
#pragma unroll
    for (int i = 0; i < 3; ++i)
#pragma unroll
        for (int tt = 0; tt < 8; ++tt)
#pragma unroll
            for (int m = 0; m < 4; ++m) acc1[i][tt][m] = 0.f;

    for (int ch = 0; ch < 3; ++ch) {          // runtime loop (code-size control)
        __syncthreads();                      // prior sW / sA readers done
        // stage W1o[:, ch*64 : ch*64+64] transposed -> sW[kk][c]
        for (int e = tid; e < 128 * 64; e += THREADS) {
            int c = e >> 6, kk = e & 63;
            sW[kk * WS + c] = W1o[c * 192 + ch * 64 + kk];
        }
#pragma unroll
        for (int i = 0; i < 3; ++i) {         // unrolled: acc1[i] stays in regs
            // build q_chunk tile [64 tok][64 r] into sA
            for (int e = tid; e < 4096; e += THREADS) {
                int t = e >> 6, r = e & 63;
                const float* p = &sP1[t * 384];
                float v;
                if (ch == 0) {
                    v = sP0[t * 128 + r] * p[i * 128 + 64 + r];            // q011
                } else if (ch == 1) {
                    v = p[i * 128 + r] * sP0[t * 128 + 64 + r];            // q101
                } else {
                    int i1 = (i + 1 < 3) ? i + 1 : i - 2;
                    int i2 = (i + 2 < 3) ? i + 2 : i - 1;
                    v = p[i1 * 128 + r] * p[i2 * 128 + 64 + r]
                      - p[i2 * 128 + r] * p[i1 * 128 + 64 + r];            // q111
                }
                sA[e] = v;
            }
            __syncthreads();                  // q tile + (i==0) W chunk ready
            gemm_tile(sA, 64, sW, 64, acc1[i], t0, lane);
            __syncthreads();                  // safe to overwrite q tile
        }
    }

    // ---- write out1 (B,N,3,C): token*384 + i*128 + c ----
#pragma unroll
    for (int i = 0; i < 3; ++i)
#pragma unroll
        for (int tt = 0; tt < 8; ++tt)
            *(float4*)&out1[(tokbase + t0 + tt) * 384 + i * 128 + lane * 4] =
                make_float4(acc1[i][tt][0], acc1[i][tt][1],
                            acc1[i][tt][2], acc1[i][tt][3]);
}

extern "C" void kernel_launch(void* const* d_in, const int* in_sizes, int n_in,
                              void* d_out, int out_size) {
    const float* z0  = (const float*)d_in[0];
    const float* z1  = (const float*)d_in[1];
    const float* W0l = (const float*)d_in[2];
    const float* b0l = (const float*)d_in[3];
    const float* W0r = (const float*)d_in[4];
    const float* b0r = (const float*)d_in[5];
    const float* W1l = (const float*)d_in[6];
    const float* W1r = (const float*)d_in[7];
    const float* W0o = (const float*)d_in[8];
    const float* b0o = (const float*)d_in[9];
    const float* W1o = (const float*)d_in[10];

    const int BN = in_sizes[0] / 128;            // 65536 tokens
    float* out0 = (float*)d_out;
    float* out1 = (float*)d_out + (long)BN * 128;

    const int smem_bytes = SMEM_FLOATS * sizeof(float);   // 231424
    cudaFuncSetAttribute(etp_kernel, cudaFuncAttributeMaxDynamicSharedMemorySize,
                         smem_bytes);

    dim3 grid(BN / TTILE);   // 1024
    dim3 block(THREADS);
    etp_kernel<<<grid, block, smem_bytes>>>(z0, z1, W0l, b0l, W0r, b0r,
                                            W1l, W1r, W0o, b0o, W1o,
                                            out0, out1);
}

// round 3
// speedup vs baseline: 1.0006x; 1.0006x over previous
#include <cuda_runtime.h>

// ============================================================================
// ElementwiseTensorProducts: fully fused single-kernel fp32 baseline.
//
//   proj0: P0[t][0:64]=z0@W0l^T+b0l, P0[t][64:128]=z0@W0r^T+b0r
//   proj1: P1[t][i*128+0:64]=z1_i@W1l^T, P1[t][i*128+64:128]=z1_i@W1r^T
//   z0_o = [p00 | p110]  -> out0 = z0_o @ W0o^T + b0o
//   z1_o = [q011|q101|q111] (per i) -> out1 = z1_o @ W1o^T (K=192, chunked 3x64)
//
// Block = 256 threads = 8 warps, tile = 64 tokens (warp w -> tokens 8w..8w+7,
// lane l -> output channels 4l..4l+3). Weights staged transposed in smem
// ([k][j], row stride 132 floats for conflict-free float4 reads). All
// intermediates live in smem; no scratch global memory needed.
// ============================================================================

#define THREADS 256
#define TTILE   64
#define WS      132          // padded row stride (floats) of transposed weights

// smem layout (floats)
#define OFF_A   0            // 8192  : z0 tile / z1_i tile / z0_o / q tile
#define OFF_P0  8192         // 8192  : proj0 result [64][128]
#define OFF_P1  16384        // 24576 : proj1 result [64][384]
#define OFF_W   40960        // 16896 : transposed weight buffer [<=128][132]
#define SMEM_FLOATS 57856    // 231424 bytes

// C[t0..t0+7][4*lane..4*lane+3] += A[t][k] * Wt[k][j]   (A reads are warp-
// uniform broadcasts; Wt reads are 128 consecutive floats per row -> no
// bank conflicts)
__device__ __forceinline__ void gemm_tile(const float* __restrict__ sA, int lda,
                                          const float* __restrict__ sW, int K,
                                          float (&acc)[8][4], int t0, int lane) {
#pragma unroll 2
    for (int k = 0; k < K; k += 4) {
        float4 a[8];
#pragma unroll
        for (int tt = 0; tt < 8; ++tt)
            a[tt] = *(const float4*)&sA[(t0 + tt) * lda + k];
#pragma unroll
        for (int kk = 0; kk < 4; ++kk) {
            float4 w = *(const float4*)&sW[(k + kk) * WS + lane * 4];
#pragma unroll
            for (int tt = 0; tt < 8; ++tt) {
                float av = (kk == 0) ? a[tt].x : (kk == 1) ? a[tt].y
                         : (kk == 2) ? a[tt].z : a[tt].w;
                acc[tt][0] = fmaf(av, w.x, acc[tt][0]);
                acc[tt][1] = fmaf(av, w.y, acc[tt][1]);
                acc[tt][2] = fmaf(av, w.z, acc[tt][2]);
                acc[tt][3] = fmaf(av, w.w, acc[tt][3]);
            }
        }
    }
}

// Load W[j][k] (row-major, K=128 cols) transposed into sW[k*WS + jofs + j]
template <int K>
__device__ __forceinline__ void load_wt(const float* __restrict__ g, float* sW,
                                        int J, int jofs, int tid) {
    for (int e = tid; e < J * K; e += THREADS) {
        int j = e / K, k = e - j * K;
        sW[k * WS + jofs + j] = g[e];
    }
}

__global__ __launch_bounds__(THREADS, 1)
void etp_kernel(const float* __restrict__ z0, const float* __restrict__ z1,
                const float* __restrict__ W0l, const float* __restrict__ b0l,
                const float* __restrict__ W0r, const float* __restrict__ b0r,
                const float* __restrict__ W1l, const float* __restrict__ W1r,
                const float* __restrict__ W0o, const float* __restrict__ b0o,
                const float* __restrict__ W1o,
                float* __restrict__ out0, float* __restrict__ out1) {
    extern __shared__ float sm[];
    float* sA  = sm + OFF_A;
    float* sP0 = sm + OFF_P0;
    float* sP1 = sm + OFF_P1;
    float* sW  = sm + OFF_W;

    const int tid  = threadIdx.x;
    const int lane = tid & 31;
    const int warp = tid >> 5;
    const int t0   = warp * 8;
    const long tokbase = (long)blockIdx.x * TTILE;

    // ---- stage z0 tile + proj0 weights ----
    {
        const float4* src = (const float4*)(z0 + tokbase * 128);
        float4* dst = (float4*)sA;
        for (int e = tid; e < TTILE * 128 / 4; e += THREADS) dst[e] = src[e];
    }
    load_wt<128>(W0l, sW, 64, 0, tid);
    load_wt<128>(W0r, sW, 64, 64, tid);
    __syncthreads();

    // ---- proj0 ----
    {
        float acc[8][4];
#pragma unroll
        for (int m = 0; m < 4; ++m) {
            int j = lane * 4 + m;
            float b = (j < 64) ? b0l[j] : b0r[j - 64];
#pragma unroll
            for (int tt = 0; tt < 8; ++tt) acc[tt][m] = b;
        }
        gemm_tile(sA, 128, sW, 128, acc, t0, lane);
#pragma unroll
        for (int tt = 0; tt < 8; ++tt)
            *(float4*)&sP0[(t0 + tt) * 128 + lane * 4] =
                make_float4(acc[tt][0], acc[tt][1], acc[tt][2], acc[tt][3]);
    }
    __syncthreads();

    // ---- proj1 (i = 0..2, weights stay resident) ----
    load_wt<128>(W1l, sW, 64, 0, tid);
    load_wt<128>(W1r, sW, 64, 64, tid);
    for (int i = 0; i < 3; ++i) {
        // stage z1[:, i, :] tile (token row stride 384 floats)
        for (int e = tid; e < 2048; e += THREADS) {
            int t = e >> 5, q = e & 31;
            ((float4*)sA)[e] =
                *(const float4*)(z1 + (tokbase + t) * 384 + i * 128 + q * 4);
        }
        __syncthreads();   // z1 tile + (first iter) W1lr ready; prior sA readers done
        float acc[8][4];
#pragma unroll
        for (int tt = 0; tt < 8; ++tt)
#pragma unroll
            for (int m = 0; m < 4; ++m) acc[tt][m] = 0.f;
        gemm_tile(sA, 128, sW, 128, acc, t0, lane);
#pragma unroll
        for (int tt = 0; tt < 8; ++tt)
            *(float4*)&sP1[(t0 + tt) * 384 + i * 128 + lane * 4] =
                make_float4(acc[tt][0], acc[tt][1], acc[tt][2], acc[tt][3]);
        __syncthreads();   // allow sA reuse next i / next phase
    }

    // ---- build z0_o = [p00 | p110] into sA; stage W0o ----
    for (int e = tid; e < 8192; e += THREADS) {
        int t = e >> 7, k = e & 127;
        float v;
        const float* p = &sP1[t * 384];
        if (k < 64) {
            v = sP0[t * 128 + k] * sP0[t * 128 + 64 + k];
        } else {
            int r = k - 64;
            v = p[r] * p[64 + r] + p[128 + r] * p[192 + r] + p[256 + r] * p[320 + r];
        }
        sA[e] = v;
    }
    load_wt<128>(W0o, sW, 128, 0, tid);
    __syncthreads();

    // ---- out0 ----
    {
        float acc[8][4];
#pragma unroll
        for (int m = 0; m < 4; ++m) {
            float b = b0o[lane * 4 + m];
#pragma unroll
            for (int tt = 0; tt < 8; ++tt) acc[tt][m] = b;
        }
        gemm_tile(sA, 128, sW, 128, acc, t0, lane);
#pragma unroll
        for (int tt = 0; tt < 8; ++tt)
            *(float4*)&out0[(tokbase + t0 + tt) * 128 + lane * 4] =
                make_float4(acc[tt][0], acc[tt][1], acc[tt][2], acc[tt][3]);
    }

    // ---- out1: K=192 GEMM, chunked into 3 slabs of 64 k each ----
    float acc1[3][8][4];
#pragma unroll
    for (int i = 0; i < 3; ++i)
#pragma unroll
        for (int tt = 0; tt < 8; ++tt)
#pragma unroll
            for (int m = 0; m < 4; ++m) acc1[i][tt][m] = 0.f;

    for (int ch = 0; ch < 3; ++ch) {          // runtime loop (code-size control)
        __syncthreads();                      // prior sW / sA readers done
        // stage W1o[:, ch*64 : ch*64+64] transposed -> sW[kk][c]
        for (int e = tid; e < 128 * 64; e += THREADS) {
            int c = e >> 6, kk = e & 63;
            sW[kk * WS + c] = W1o[c * 192 + ch * 64 + kk];
        }
#pragma unroll
        for (int i = 0; i < 3; ++i) {         // unrolled: acc1[i] stays in regs
            // build q_chunk tile [64 tok][64 r] into sA
            for (int e = tid; e < 4096; e += THREADS) {
                int t = e >> 6, r = e & 63;
                const float* p = &sP1[t * 384];
                float v;
                if (ch == 0) {
                    v = sP0[t * 128 + r] * p[i * 128 + 64 + r];            // q011
                } else if (ch == 1) {
                    v = p[i * 128 + r] * sP0[t * 128 + 64 + r];            // q101
                } else {
                    int i1 = (i + 1 < 3) ? i + 1 : i - 2;
                    int i2 = (i + 2 < 3) ? i + 2 : i - 1;
                    v = p[i1 * 128 + r] * p[i2 * 128 + 64 + r]
                      - p[i2 * 128 + r] * p[i1 * 128 + 64 + r];            // q111
                }
                sA[e] = v;
            }
            __syncthreads();                  // q tile + (i==0) W chunk ready
            gemm_tile(sA, 64, sW, 64, acc1[i], t0, lane);
            __syncthreads();                  // safe to overwrite q tile
        }
    }

    // ---- write out1 (B,N,3,C): token*384 + i*128 + c ----
#pragma unroll
    for (int i = 0; i < 3; ++i)
#pragma unroll
        for (int tt = 0; tt < 8; ++tt)
            *(float4*)&out1[(tokbase + t0 + tt) * 384 + i * 128 + lane * 4] =
                make_float4(acc1[i][tt][0], acc1[i][tt][1],
                            acc1[i][tt][2], acc1[i][tt][3]);
}

extern "C" void kernel_launch(void* const* d_in, const int* in_sizes, int n_in,
                              void* d_out, int out_size) {
    const float* z0  = (const float*)d_in[0];
    const float* z1  = (const float*)d_in[1];
    const float* W0l = (const float*)d_in[2];
    const float* b0l = (const float*)d_in[3];
    const float* W0r = (const float*)d_in[4];
    const float* b0r = (const float*)d_in[5];
    const float* W1l = (const float*)d_in[6];
    const float* W1r = (const float*)d_in[7];
    const float* W0o = (const float*)d_in[8];
    const float* b0o = (const float*)d_in[9];
    const float* W1o = (const float*)d_in[10];

    const int BN = in_sizes[0] / 128;            // 65536 tokens
    float* out0 = (float*)d_out;
    float* out1 = (float*)d_out + (long)BN * 128;

    const int smem_bytes = SMEM_FLOATS * sizeof(float);   // 231424
    cudaFuncSetAttribute(etp_kernel, cudaFuncAttributeMaxDynamicSharedMemorySize,
                         smem_bytes);

    dim3 grid(BN / TTILE);   // 1024
    dim3 block(THREADS);
    etp_kernel<<<grid, block, smem_bytes>>>(z0, z1, W0l, b0l, W0r, b0r,
                                            W1l, W1r, W0o, b0o, W1o,
                                            out0, out1);
}

// round 4
// speedup vs baseline: 1.0046x; 1.0040x over previous
#include <cuda_runtime.h>

// ============================================================================
// ElementwiseTensorProducts: fully fused single-kernel fp32 baseline.
//
//   proj0: P0[t][0:64]=z0@W0l^T+b0l, P0[t][64:128]=z0@W0r^T+b0r
//   proj1: P1[t][i*128+0:64]=z1_i@W1l^T, P1[t][i*128+64:128]=z1_i@W1r^T
//   z0_o = [p00 | p110]  -> out0 = z0_o @ W0o^T + b0o
//   z1_o = [q011|q101|q111] (per i) -> out1 = z1_o @ W1o^T (K=192, chunked 3x64)
//
// Block = 256 threads = 8 warps, tile = 64 tokens (warp w -> tokens 8w..8w+7,
// lane l -> output channels 4l..4l+3). Weights staged transposed in smem
// ([k][j], row stride 132 floats for conflict-free float4 reads). All
// intermediates live in smem; no scratch global memory needed.
// ============================================================================

#define THREADS 256
#define TTILE   64
#define WS      132          // padded row stride (floats) of transposed weights

// smem layout (floats)
#define OFF_A   0            // 8192  : z0 tile / z1_i tile / z0_o / q tile
#define OFF_P0  8192         // 8192  : proj0 result [64][128]
#define OFF_P1  16384        // 24576 : proj1 result [64][384]
#define OFF_W   40960        // 16896 : transposed weight buffer [<=128][132]
#define SMEM_FLOATS 57856    // 231424 bytes

// C[t0..t0+7][4*lane..4*lane+3] += A[t][k] * Wt[k][j]   (A reads are warp-
// uniform broadcasts; Wt reads are 128 consecutive floats per row -> no
// bank conflicts)
__device__ __forceinline__ void gemm_tile(const float* __restrict__ sA, int lda,
                                          const float* __restrict__ sW, int K,
                                          float (&acc)[8][4], int t0, int lane) {
#pragma unroll 2
    for (int k = 0; k < K; k += 4) {
        float4 a[8];
#pragma unroll
        for (int tt = 0; tt < 8; ++tt)
            a[tt] = *(const float4*)&sA[(t0 + tt) * lda + k];
#pragma unroll
        for (int kk = 0; kk < 4; ++kk) {
            float4 w = *(const float4*)&sW[(k + kk) * WS + lane * 4];
#pragma unroll
            for (int tt = 0; tt < 8; ++tt) {
                float av = (kk == 0) ? a[tt].x : (kk == 1) ? a[tt].y
                         : (kk == 2) ? a[tt].z : a[tt].w;
                acc[tt][0] = fmaf(av, w.x, acc[tt][0]);
                acc[tt][1] = fmaf(av, w.y, acc[tt][1]);
                acc[tt][2] = fmaf(av, w.z, acc[tt][2]);
                acc[tt][3] = fmaf(av, w.w, acc[tt][3]);
            }
        }
    }
}

// Load W[j][k] (row-major, K=128 cols) transposed into sW[k*WS + jofs + j]
template <int K>
__device__ __forceinline__ void load_wt(const float* __restrict__ g, float* sW,
                                        int J, int jofs, int tid) {
    for (int e = tid; e < J * K; e += THREADS) {
        int j = e / K, k = e - j * K;
        sW[k * WS + jofs + j] = g[e];
    }
}

__global__ __launch_bounds__(THREADS, 1)
void etp_kernel(const float* __restrict__ z0, const float* __restrict__ z1,
                const float* __restrict__ W0l, const float* __restrict__ b0l,
                const float* __restrict__ W0r, const float* __restrict__ b0r,
                const float* __restrict__ W1l, const float* __restrict__ W1r,
                const float* __restrict__ W0o, const float* __restrict__ b0o,
                const float* __restrict__ W1o,
                float* __restrict__ out0, float* __restrict__ out1) {
    extern __shared__ float sm[];
    float* sA  = sm + OFF_A;
    float* sP0 = sm + OFF_P0;
    float* sP1 = sm + OFF_P1;
    float* sW  = sm + OFF_W;

    const int tid  = threadIdx.x;
    const int lane = tid & 31;
    const int warp = tid >> 5;
    const int t0   = warp * 8;
    const long tokbase = (long)blockIdx.x * TTILE;

    // ---- stage z0 tile + proj0 weights ----
    {
        const float4* src = (const float4*)(z0 + tokbase * 128);
        float4* dst = (float4*)sA;
        for (int e = tid; e < TTILE * 128 / 4; e += THREADS) dst[e] = src[e];
    }
    load_wt<128>(W0l, sW, 64, 0, tid);
    load_wt<128>(W0r, sW, 64, 64, tid);
    __syncthreads();

    // ---- proj0 ----
    {
        float acc[8][4];
#pragma unroll
        for (int m = 0; m < 4; ++m) {
            int j = lane * 4 + m;
            float b = (j < 64) ? b0l[j] : b0r[j - 64];
#pragma unroll
            for (int tt = 0; tt < 8; ++tt) acc[tt][m] = b;
        }
        gemm_tile(sA, 128, sW, 128, acc, t0, lane);
#pragma unroll
        for (int tt = 0; tt < 8; ++tt)
            *(float4*)&sP0[(t0 + tt) * 128 + lane * 4] =
                make_float4(acc[tt][0], acc[tt][1], acc[tt][2], acc[tt][3]);
    }
    __syncthreads();

    // ---- proj1 (i = 0..2, weights stay resident) ----
    load_wt<128>(W1l, sW, 64, 0, tid);
    load_wt<128>(W1r, sW, 64, 64, tid);
    for (int i = 0; i < 3; ++i) {
        // stage z1[:, i, :] tile (token row stride 384 floats)
        for (int e = tid; e < 2048; e += THREADS) {
            int t = e >> 5, q = e & 31;
            ((float4*)sA)[e] =
                *(const float4*)(z1 + (tokbase + t) * 384 + i * 128 + q * 4);
        }
        __syncthreads();   // z1 tile + (first iter) W1lr ready; prior sA readers done
        float acc[8][4];
#pragma unroll
        for (int tt = 0; tt < 8; ++tt)
#pragma unroll
            for (int m = 0; m < 4; ++m) acc[tt][m] = 0.f;
        gemm_tile(sA, 128, sW, 128, acc, t0, lane);
#pragma unroll
        for (int tt = 0; tt < 8; ++tt)
            *(float4*)&sP1[(t0 + tt) * 384 + i * 128 + lane * 4] =
                make_float4(acc[tt][0], acc[tt][1], acc[tt][2], acc[tt][3]);
        __syncthreads();   // allow sA reuse next i / next phase
    }

    // ---- build z0_o = [p00 | p110] into sA; stage W0o ----
    for (int e = tid; e < 8192; e += THREADS) {
        int t = e >> 7, k = e & 127;
        float v;
        const float* p = &sP1[t * 384];
        if (k < 64) {
            v = sP0[t * 128 + k] * sP0[t * 128 + 64 + k];
        } else {
            int r = k - 64;
            v = p[r] * p[64 + r] + p[128 + r] * p[192 + r] + p[256 + r] * p[320 + r];
        }
        sA[e] = v;
    }
    load_wt<128>(W0o, sW, 128, 0, tid);
    __syncthreads();

    // ---- out0 ----
    {
        float acc[8][4];
#pragma unroll
        for (int m = 0; m < 4; ++m) {
            float b = b0o[lane * 4 + m];
#pragma unroll
            for (int tt = 0; tt < 8; ++tt) acc[tt][m] = b;
        }
        gemm_tile(sA, 128, sW, 128, acc, t0, lane);
#pragma unroll
        for (int tt = 0; tt < 8; ++tt)
            *(float4*)&out0[(tokbase + t0 + tt) * 128 + lane * 4] =
                make_float4(acc[tt][0], acc[tt][1], acc[tt][2], acc[tt][3]);
    }

    // ---- out1: K=192 GEMM, chunked into 3 slabs of 64 k each ----
    float acc1[3][8][4];
#pragma unroll
    for (int i = 0; i < 3; ++i)
#pragma unroll
        for (int tt = 0; tt < 8; ++tt)
#pragma unroll
            for (int m = 0; m < 4; ++m) acc1[i][tt][m] = 0.f;

    for (int ch = 0; ch < 3; ++ch) {          // runtime loop (code-size control)
        __syncthreads();                      // prior sW / sA readers done
        // stage W1o[:, ch*64 : ch*64+64] transposed -> sW[kk][c]
        for (int e = tid; e < 128 * 64; e += THREADS) {
            int c = e >> 6, kk = e & 63;
            sW[kk * WS + c] = W1o[c * 192 + ch * 64 + kk];
        }
#pragma unroll
        for (int i = 0; i < 3; ++i) {         // unrolled: acc1[i] stays in regs
            // build q_chunk tile [64 tok][64 r] into sA
            for (int e = tid; e < 4096; e += THREADS) {
                int t = e >> 6, r = e & 63;
                const float* p = &sP1[t * 384];
                float v;
                if (ch == 0) {
                    v = sP0[t * 128 + r] * p[i * 128 + 64 + r];            // q011
                } else if (ch == 1) {
                    v = p[i * 128 + r] * sP0[t * 128 + 64 + r];            // q101
                } else {
                    int i1 = (i + 1 < 3) ? i + 1 : i - 2;
                    int i2 = (i + 2 < 3) ? i + 2 : i - 1;
                    v = p[i1 * 128 + r] * p[i2 * 128 + 64 + r]
                      - p[i2 * 128 + r] * p[i1 * 128 + 64 + r];            // q111
                }
                sA[e] = v;
            }
            __syncthreads();                  // q tile + (i==0) W chunk ready
            gemm_tile(sA, 64, sW, 64, acc1[i], t0, lane);
            __syncthreads();                  // safe to overwrite q tile
        }
    }

    // ---- write out1 (B,N,3,C): token*384 + i*128 + c ----
#pragma unroll
    for (int i = 0; i < 3; ++i)
#pragma unroll
        for (int tt = 0; tt < 8; ++tt)
            *(float4*)&out1[(tokbase + t0 + tt) * 384 + i * 128 + lane * 4] =
                make_float4(acc1[i][tt][0], acc1[i][tt][1],
                            acc1[i][tt][2], acc1[i][tt][3]);
}

extern "C" void kernel_launch(void* const* d_in, const int* in_sizes, int n_in,
                              void* d_out, int out_size) {
    const float* z0  = (const float*)d_in[0];
    const float* z1  = (const float*)d_in[1];
    const float* W0l = (const float*)d_in[2];
    const float* b0l = (const float*)d_in[3];
    const float* W0r = (const float*)d_in[4];
    const float* b0r = (const float*)d_in[5];
    const float* W1l = (const float*)d_in[6];
    const float* W1r = (const float*)d_in[7];
    const float* W0o = (const float*)d_in[8];
    const float* b0o = (const float*)d_in[9];
    const float* W1o = (const float*)d_in[10];

    const int BN = in_sizes[0] / 128;            // 65536 tokens
    float* out0 = (float*)d_out;
    float* out1 = (float*)d_out + (long)BN * 128;

    const int smem_bytes = SMEM_FLOATS * sizeof(float);   // 231424
    cudaFuncSetAttribute(etp_kernel, cudaFuncAttributeMaxDynamicSharedMemorySize,
                         smem_bytes);

    dim3 grid(BN / TTILE);   // 1024
    dim3 block(THREADS);
    etp_kernel<<<grid, block, smem_bytes>>>(z0, z1, W0l, b0l, W0r, b0r,
                                            W1l, W1r, W0o, b0o, W1o,
                                            out0, out1);
}